// round 1
// baseline (speedup 1.0000x reference)
#include <cuda_runtime.h>
#include <cuda_bf16.h>
#include <cstdint>

// Problem dims (fixed by the dataset)
#define BB 16
#define SS 2048
#define DD 128
#define UU 128

// Scratch (static __device__ — allocation-guard safe)
__device__ float g_qT[(size_t)BB * UU * SS];   // [b][u][i]  16MB
__device__ float g_kT[(size_t)BB * UU * SS];   // [b][u][j]  16MB
__device__ uint4 g_E[(size_t)BB * SS * SS / 8];// bf16 E[b][i][j], 128MB
__device__ float g_l[BB * SS];
__device__ float g_u[BB * SS];
__device__ float g_w[BB * SS];

// ---------------------------------------------------------------------------
// Kernel A: q = x@Wq, k = x@Wk, stored TRANSPOSED (u-major) so the scores
// kernel's smem tiles load with zero bank conflicts. Also zeroes g_l.
// block = 128 threads (one per u), 32 rows per block.
// ---------------------------------------------------------------------------
__global__ void proj_kernel(const float* __restrict__ x,
                            const float* __restrict__ Wq,
                            const float* __restrict__ Wk) {
    extern __shared__ float sm[];          // 128*33 floats = 16896 B
    const int tid  = threadIdx.x;          // 0..127  (u index)
    const int row0 = blockIdx.x * 32;      // global row in [0, B*S)
    const int b    = row0 / SS;
    const int i0   = row0 % SS;

    // zero g_l (1024 blocks * 128 threads == 131072 >= 32768)
    int gtid = blockIdx.x * 128 + tid;
    if (gtid < BB * SS) g_l[gtid] = 0.f;

    // phase 1: stage x rows (32 x 128 floats) — coalesced
    #pragma unroll
    for (int k = 0; k < 32; k++) {
        int e = tid + 128 * k;
        sm[e] = x[(size_t)row0 * DD + e];
    }
    __syncthreads();

    float qa[32], ka[32];
    #pragma unroll
    for (int r = 0; r < 32; r++) { qa[r] = 0.f; ka[r] = 0.f; }

    const int u = tid;
    #pragma unroll 4
    for (int d4 = 0; d4 < 32; d4++) {
        float wq0 = Wq[(4 * d4 + 0) * UU + u];
        float wq1 = Wq[(4 * d4 + 1) * UU + u];
        float wq2 = Wq[(4 * d4 + 2) * UU + u];
        float wq3 = Wq[(4 * d4 + 3) * UU + u];
        float wk0 = Wk[(4 * d4 + 0) * UU + u];
        float wk1 = Wk[(4 * d4 + 1) * UU + u];
        float wk2 = Wk[(4 * d4 + 2) * UU + u];
        float wk3 = Wk[(4 * d4 + 3) * UU + u];
        #pragma unroll
        for (int r = 0; r < 32; r++) {
            float4 xv = *reinterpret_cast<float4*>(&sm[r * 128 + d4 * 4]);
            qa[r] += xv.x * wq0 + xv.y * wq1 + xv.z * wq2 + xv.w * wq3;
            ka[r] += xv.x * wk0 + xv.y * wk1 + xv.z * wk2 + xv.w * wk3;
        }
    }
    __syncthreads();

    // phase 2a: transpose q through smem (pad 33 -> conflict-free)
    #pragma unroll
    for (int r = 0; r < 32; r++) sm[u * 33 + r] = qa[r];
    __syncthreads();
    #pragma unroll
    for (int k = 0; k < 32; k++) {
        int u_o = (tid >> 5) + 4 * k;
        int il  = tid & 31;
        g_qT[((size_t)b * UU + u_o) * SS + i0 + il] = sm[u_o * 33 + il];
    }
    __syncthreads();

    // phase 2b: transpose k
    #pragma unroll
    for (int r = 0; r < 32; r++) sm[u * 33 + r] = ka[r];
    __syncthreads();
    #pragma unroll
    for (int k = 0; k < 32; k++) {
        int u_o = (tid >> 5) + 4 * k;
        int il  = tid & 31;
        g_kT[((size_t)b * UU + u_o) * SS + i0 + il] = sm[u_o * 33 + il];
    }
}

// ---------------------------------------------------------------------------
// Kernel B: the big one. Per CTA: 128x128 tile of scores for one batch,
// K=128 full-depth smem tiles (u-major, so loads AND frag reads are clean).
// Epilogue: e = exp(s/sqrt(U)) -> bf16 store to g_E, row-sums -> atomic g_l.
// block = 256 threads, 8x8 register micro-tile, 128KB dynamic smem.
// ---------------------------------------------------------------------------
__global__ void scores_kernel() {
    extern __shared__ float sm[];
    float* As = sm;                // As[u][i]  128x128
    float* Bs = sm + 128 * 128;    // Bs[u][j]  128x128

    const int b  = blockIdx.z;
    const int i0 = blockIdx.y * 128;
    const int j0 = blockIdx.x * 128;
    const int tid = threadIdx.x;

    // load tiles: coalesced global float4, conflict-free STS
    {
        const float* qb = g_qT + (size_t)b * UU * SS;
        const float* kb = g_kT + (size_t)b * UU * SS;
        #pragma unroll
        for (int k = 0; k < 16; k++) {
            int f  = tid + 256 * k;     // float4 index within tile
            int u  = f >> 5;
            int ic = f & 31;
            reinterpret_cast<float4*>(As)[u * 32 + ic] =
                *reinterpret_cast<const float4*>(qb + (size_t)u * SS + i0 + ic * 4);
            reinterpret_cast<float4*>(Bs)[u * 32 + ic] =
                *reinterpret_cast<const float4*>(kb + (size_t)u * SS + j0 + ic * 4);
        }
    }
    __syncthreads();

    const int tx = tid & 15;
    const int ty = tid >> 4;

    float acc[8][8];
    #pragma unroll
    for (int r = 0; r < 8; r++)
        #pragma unroll
        for (int c = 0; c < 8; c++) acc[r][c] = 0.f;

    #pragma unroll 2
    for (int u = 0; u < 128; u++) {
        float4 a0 = reinterpret_cast<float4*>(As + u * 128 + ty * 8)[0];
        float4 a1 = reinterpret_cast<float4*>(As + u * 128 + ty * 8)[1];
        float4 b0 = reinterpret_cast<float4*>(Bs + u * 128 + tx * 8)[0];
        float4 b1 = reinterpret_cast<float4*>(Bs + u * 128 + tx * 8)[1];
        float av[8] = {a0.x, a0.y, a0.z, a0.w, a1.x, a1.y, a1.z, a1.w};
        float bv[8] = {b0.x, b0.y, b0.z, b0.w, b1.x, b1.y, b1.z, b1.w};
        #pragma unroll
        for (int r = 0; r < 8; r++)
            #pragma unroll
            for (int c = 0; c < 8; c++)
                acc[r][c] += av[r] * bv[c];
    }

    // epilogue: exp, bf16 store, row sums
    const float RSCALE = 0.08838834764831845f;  // 1/sqrt(128)
    float rsum[8];
    #pragma unroll
    for (int r = 0; r < 8; r++) {
        union { __nv_bfloat16 h[8]; uint4 v; } pk;
        float rs = 0.f;
        #pragma unroll
        for (int c = 0; c < 8; c++) {
            float ef = __expf(acc[r][c] * RSCALE);
            __nv_bfloat16 bh = __float2bfloat16(ef);
            pk.h[c] = bh;
            rs += __bfloat162float(bh);   // sum the ROUNDED values (consistency)
        }
        rsum[r] = rs;
        size_t eidx = ((size_t)(b * SS + i0 + ty * 8 + r) * SS + j0 + tx * 8) / 8;
        g_E[eidx] = pk.v;
    }

    // reduce row sums over tx (low 4 lane bits), then atomic to g_l
    #pragma unroll
    for (int r = 0; r < 8; r++) {
        float rs = rsum[r];
        rs += __shfl_xor_sync(0xffffffffu, rs, 1);
        rs += __shfl_xor_sync(0xffffffffu, rs, 2);
        rs += __shfl_xor_sync(0xffffffffu, rs, 4);
        rs += __shfl_xor_sync(0xffffffffu, rs, 8);
        if (tx == 0) atomicAdd(&g_l[b * SS + i0 + ty * 8 + r], rs);
    }
}

// ---------------------------------------------------------------------------
// Kernel C: u = sigmoid(theta - mu*t) / l ; zero g_w and d_out
// ---------------------------------------------------------------------------
__global__ void uw_kernel(const float* __restrict__ t,
                          const float* __restrict__ theta,
                          const float* __restrict__ mu,
                          float* __restrict__ out) {
    int idx = blockIdx.x * 256 + threadIdx.x;
    if (idx < BB * SS) {
        int s = idx & (SS - 1);
        float z  = theta[s] - mu[s] * t[idx];
        float tf = 1.f / (1.f + __expf(-z));
        g_u[idx] = tf / g_l[idx];
        g_w[idx] = 0.f;
    }
    if (idx < BB * DD) out[idx] = 0.f;
}

// ---------------------------------------------------------------------------
// Kernel D: w[b][j] = sum_i E[b][i][j] * u[b][i]   (134MB streamed, mem-bound)
// grid (isplit=4, jt=4, b=16), block 256, 2 j's per thread (bf16x2 loads)
// ---------------------------------------------------------------------------
__global__ void wsum_kernel() {
    const int b  = blockIdx.z;
    const int jt = blockIdx.y;
    const int is = blockIdx.x;
    const int j2 = jt * 256 + threadIdx.x;   // pair index: j = 2*j2, 2*j2+1

    const __nv_bfloat162* Eb =
        reinterpret_cast<const __nv_bfloat162*>(g_E) + (size_t)b * SS * (SS / 2);
    const float* ub = g_u + b * SS;

    float acc0 = 0.f, acc1 = 0.f;
    int ib = is * 512;
    #pragma unroll 8
    for (int i = ib; i < ib + 512; i++) {
        __nv_bfloat162 ev = Eb[(size_t)i * (SS / 2) + j2];
        float uu = ub[i];
        acc0 += __low2float(ev) * uu;
        acc1 += __high2float(ev) * uu;
    }
    atomicAdd(&g_w[b * SS + 2 * j2 + 0], acc0);
    atomicAdd(&g_w[b * SS + 2 * j2 + 1], acc1);
}

// ---------------------------------------------------------------------------
// Kernel E: v[b][d] = sum_j w[b][j] * x[b][j][d]
// grid (jsplit=8, b=16), block 128 (one d per thread)
// ---------------------------------------------------------------------------
__global__ void v_kernel(const float* __restrict__ x, float* __restrict__ out) {
    const int b  = blockIdx.y;
    const int js = blockIdx.x;
    const int d  = threadIdx.x;
    const float* wb = g_w + b * SS;
    float acc = 0.f;
    int j0 = js * 256;
    #pragma unroll 4
    for (int j = j0; j < j0 + 256; j++)
        acc += wb[j] * x[((size_t)b * SS + j) * DD + d];
    atomicAdd(&out[b * DD + d], acc);
}

// ---------------------------------------------------------------------------
extern "C" void kernel_launch(void* const* d_in, const int* in_sizes, int n_in,
                              void* d_out, int out_size) {
    const float* x     = (const float*)d_in[0];  // (16,2048,128)
    const float* t     = (const float*)d_in[1];  // (16,2048)
    const float* Wq    = (const float*)d_in[2];  // (128,128)
    const float* Wk    = (const float*)d_in[3];  // (128,128)
    const float* theta = (const float*)d_in[4];  // (1,2048)
    const float* mu    = (const float*)d_in[5];  // (1,2048)
    float* out = (float*)d_out;                  // (16,128)

    static bool attr_done = false;
    if (!attr_done) {
        cudaFuncSetAttribute(scores_kernel,
                             cudaFuncAttributeMaxDynamicSharedMemorySize, 131072);
        attr_done = true;
    }

    // A: projections (+ zero g_l)
    proj_kernel<<<(BB * SS) / 32, 128, 128 * 33 * sizeof(float)>>>(x, Wq, Wk);
    // B: exp(QK^T/sqrt(U)) -> g_E (bf16), row sums -> g_l
    scores_kernel<<<dim3(SS / 128, SS / 128, BB), 256, 131072>>>();
    // C: u = sigmoid/l, zero w & out
    uw_kernel<<<(BB * SS + 255) / 256, 256>>>(t, theta, mu, out);
    // D: w = E^T u
    wsum_kernel<<<dim3(4, 4, BB), 256>>>();
    // E: v = x^T w
    v_kernel<<<dim3(8, BB), 128>>>(x, out);
}

// round 5
// speedup vs baseline: 3.7753x; 3.7753x over previous
#include <cuda_runtime.h>
#include <cuda_bf16.h>
#include <cstdint>

#define BB 16
#define SS 2048
#define DD 128
#define UU 128

// ---------------------------------------------------------------------------
// Scratch (static __device__ — allocation-guard safe)
// ---------------------------------------------------------------------------
__device__ __nv_bfloat16 g_qb[(size_t)BB * SS * UU];   // q' = (x Wq)*log2e/sqrt(U), bf16 [row][u]
__device__ __nv_bfloat16 g_kb[(size_t)BB * SS * UU];   // k  =  x Wk, bf16 [row][u]
__device__ __nv_bfloat16 g_WT[256 * DD];               // [Wq*c | Wk] transposed: [n][d]
__device__ uint4 g_E[(size_t)BB * SS * SS / 8];        // bf16 E[b][i][j], 128MB
__device__ float g_l[BB * SS];
__device__ float g_u[BB * SS];
__device__ float g_w[BB * SS];

// ---------------------------------------------------------------------------
// helpers
// ---------------------------------------------------------------------------
__device__ __forceinline__ uint32_t smem_u32(const void* p) {
    uint32_t a;
    asm("{ .reg .u64 t; cvta.to.shared.u64 t, %1; cvt.u32.u64 %0, t; }" : "=r"(a) : "l"(p));
    return a;
}
__device__ __forceinline__ float ex2f(float x) {
    float r; asm("ex2.approx.f32 %0, %1;" : "=f"(r) : "f"(x)); return r;
}
__device__ __forceinline__ void ldmx4(uint32_t* r, uint32_t addr) {
    asm volatile("ldmatrix.sync.aligned.m8n8.x4.shared.b16 {%0,%1,%2,%3}, [%4];"
                 : "=r"(r[0]), "=r"(r[1]), "=r"(r[2]), "=r"(r[3]) : "r"(addr));
}
__device__ __forceinline__ void mma16816(float* c, const uint32_t* a, uint32_t b0, uint32_t b1) {
    asm volatile(
        "mma.sync.aligned.m16n8k16.row.col.f32.bf16.bf16.f32 "
        "{%0,%1,%2,%3}, {%4,%5,%6,%7}, {%8,%9}, {%0,%1,%2,%3};"
        : "+f"(c[0]), "+f"(c[1]), "+f"(c[2]), "+f"(c[3])
        : "r"(a[0]), "r"(a[1]), "r"(a[2]), "r"(a[3]), "r"(b0), "r"(b1));
}
__device__ __forceinline__ uint32_t pack_bf16x2(float lo, float hi) {
    uint32_t r;
    asm("cvt.rn.bf16x2.f32 %0, %1, %2;" : "=r"(r) : "f"(hi), "f"(lo));
    return r;
}

// Swizzled smem tile: 128 rows x 16 uint4 chunks (256B/row), chunk ^= (row&7).
// Conflict-free for both row-major uint4 fills and ldmatrix 8-row column reads.
__device__ __forceinline__ int tidx(int row, int chunk) {
    return row * 16 + (chunk ^ (row & 7));
}
// byte address of (row, chunk) relative to a smem uint32 base address
__device__ __forceinline__ uint32_t taddr(uint32_t base, int row, int chunk) {
    return base + (uint32_t)tidx(row, chunk) * 16u;
}

// ---------------------------------------------------------------------------
// prep: zero g_l; g_WT[n][d] = (n<128 ? Wq[d][n]*C : Wk[d][n-128]) as bf16
// ---------------------------------------------------------------------------
__global__ void prep_kernel(const float* __restrict__ Wq, const float* __restrict__ Wk) {
    const float C_FOLD = 0.12751744695704165f;  // log2(e)/sqrt(128)
    int idx = blockIdx.x * 256 + threadIdx.x;   // 0..32767
    g_l[idx] = 0.f;
    int n = idx >> 7, d = idx & 127;
    float v = (n < 128) ? Wq[d * 128 + n] * C_FOLD : Wk[d * 128 + (n - 128)];
    g_WT[idx] = __float2bfloat16(v);
}

// ---------------------------------------------------------------------------
// Shared GEMM core: per CTA 128x128 bf16 mma.sync GEMM, K=128 resident.
// 8 warps: warp_m = wid&3 (32 rows), warp_n = wid>>2 (64 cols).
// Returns accumulators in c[2][8][4]; A/B tiles must already be in smem.
// ---------------------------------------------------------------------------
struct Frag { float c[2][8][4]; };

__device__ __forceinline__ void gemm_128x128(uint32_t aBase, uint32_t bBase, Frag& F) {
    const int lane = threadIdx.x & 31, wid = threadIdx.x >> 5;
    const int wm = (wid & 3) * 32, wn = (wid >> 2) * 64;

    #pragma unroll
    for (int mt = 0; mt < 2; mt++)
        #pragma unroll
        for (int nt = 0; nt < 8; nt++)
            #pragma unroll
            for (int e = 0; e < 4; e++) F.c[mt][nt][e] = 0.f;

    const int l7 = lane & 7, lhi = lane >> 3;

    #pragma unroll
    for (int ks = 0; ks < 8; ks++) {
        uint32_t a[2][4];
        #pragma unroll
        for (int mt = 0; mt < 2; mt++) {
            int row = wm + mt * 16 + l7 + (lhi & 1) * 8;
            int chunk = 2 * ks + (lhi >> 1);
            ldmx4(a[mt], taddr(aBase, row, chunk));
        }
        uint32_t bfr[4][4];
        #pragma unroll
        for (int np = 0; np < 4; np++) {
            int row = wn + np * 16 + l7 + (lhi >> 1) * 8;
            int chunk = 2 * ks + (lhi & 1);
            ldmx4(bfr[np], taddr(bBase, row, chunk));
        }
        #pragma unroll
        for (int mt = 0; mt < 2; mt++)
            #pragma unroll
            for (int np = 0; np < 4; np++) {
                mma16816(F.c[mt][2 * np + 0], a[mt], bfr[np][0], bfr[np][1]);
                mma16816(F.c[mt][2 * np + 1], a[mt], bfr[np][2], bfr[np][3]);
            }
    }
}

// store one packed bf16x2 into the staging tile at (row, col) [col even, 0..127]
__device__ __forceinline__ void stage_sts(char* sm, int row, int col, uint32_t v) {
    uint32_t byte = (uint32_t)tidx(row, col >> 3) * 16u + (uint32_t)(col & 7) * 2u;
    *reinterpret_cast<uint32_t*>(sm + byte) = v;
}

// ---------------------------------------------------------------------------
// proj: per CTA: rows r0..r0+127 of x (bf16-converted) @ g_WT half -> 128x128
// blockIdx.x = row tile (0..255), blockIdx.y = half (0: q', 1: k)
// ---------------------------------------------------------------------------
__global__ void __launch_bounds__(256) proj_kernel(const float* __restrict__ x) {
    extern __shared__ char sm[];
    char* As = sm;
    char* Bs = sm + 32768;
    uint32_t aBase = smem_u32(As), bBase = smem_u32(Bs);

    const int tid = threadIdx.x;
    const int r0 = blockIdx.x * 128;
    const int nsel = blockIdx.y;

    // A: x rows, fp32 -> bf16
    {
        const float4* xs = reinterpret_cast<const float4*>(x + (size_t)r0 * DD);
        #pragma unroll
        for (int it = 0; it < 8; it++) {
            int idx = tid + 256 * it;             // uint4 chunk id, 0..2047
            int row = idx >> 4, chunk = idx & 15;
            float4 f0 = xs[row * 32 + chunk * 2];
            float4 f1 = xs[row * 32 + chunk * 2 + 1];
            uint4 o;
            o.x = pack_bf16x2(f0.x, f0.y);
            o.y = pack_bf16x2(f0.z, f0.w);
            o.z = pack_bf16x2(f1.x, f1.y);
            o.w = pack_bf16x2(f1.z, f1.w);
            reinterpret_cast<uint4*>(As)[tidx(row, chunk)] = o;
        }
    }
    // B: g_WT rows nsel*128 .. +127
    {
        const uint4* ws = reinterpret_cast<const uint4*>(g_WT) + nsel * 128 * 16;
        #pragma unroll
        for (int it = 0; it < 8; it++) {
            int idx = tid + 256 * it;
            int row = idx >> 4, chunk = idx & 15;
            reinterpret_cast<uint4*>(Bs)[tidx(row, chunk)] = ws[idx];
        }
    }
    __syncthreads();

    Frag F;
    gemm_128x128(aBase, bBase, F);
    __syncthreads();   // everyone done reading smem

    // stage bf16 results (row = i, col = n) into As
    const int lane = tid & 31, wid = tid >> 5;
    const int wm = (wid & 3) * 32, wn = (wid >> 2) * 64;
    const int lr = lane >> 2, lc = (lane & 3) * 2;
    #pragma unroll
    for (int mt = 0; mt < 2; mt++) {
        #pragma unroll
        for (int nt = 0; nt < 8; nt++) {
            int row = wm + mt * 16 + lr;
            int col = wn + nt * 8 + lc;
            float* cc = F.c[mt][nt];
            stage_sts(As, row,     col, pack_bf16x2(cc[0], cc[1]));
            stage_sts(As, row + 8, col, pack_bf16x2(cc[2], cc[3]));
        }
    }
    __syncthreads();

    // coalesced store: row-major [row][u] bf16
    uint4* dst = reinterpret_cast<uint4*>(nsel ? g_kb : g_qb) + (size_t)r0 * 16;
    #pragma unroll
    for (int it = 0; it < 8; it++) {
        int idx = tid + 256 * it;
        int row = idx >> 4, chunk = idx & 15;
        dst[idx] = reinterpret_cast<uint4*>(As)[tidx(row, chunk)];
    }
}

// ---------------------------------------------------------------------------
// scores: per CTA 128(i) x 128(j) of E = exp2(q'.k) for one batch.
// grid (16, 16, 16), block 256.
// ---------------------------------------------------------------------------
__global__ void __launch_bounds__(256) scores_kernel() {
    extern __shared__ char sm[];
    char* As = sm;
    char* Bs = sm + 32768;
    uint32_t aBase = smem_u32(As), bBase = smem_u32(Bs);

    const int tid = threadIdx.x;
    const int b = blockIdx.z, i0 = blockIdx.y * 128, j0 = blockIdx.x * 128;

    {
        const uint4* qs = reinterpret_cast<const uint4*>(g_qb) + (size_t)(b * SS + i0) * 16;
        const uint4* ks = reinterpret_cast<const uint4*>(g_kb) + (size_t)(b * SS + j0) * 16;
        #pragma unroll
        for (int it = 0; it < 8; it++) {
            int idx = tid + 256 * it;
            int row = idx >> 4, chunk = idx & 15;
            reinterpret_cast<uint4*>(As)[tidx(row, chunk)] = qs[idx];
            reinterpret_cast<uint4*>(Bs)[tidx(row, chunk)] = ks[idx];
        }
    }
    __syncthreads();

    Frag F;
    gemm_128x128(aBase, bBase, F);
    __syncthreads();

    // epilogue: exp2, stage bf16, row sums
    const int lane = tid & 31, wid = tid >> 5;
    const int wm = (wid & 3) * 32, wn = (wid >> 2) * 64;
    const int lr = lane >> 2, lc = (lane & 3) * 2;

    float rs[2][2];  // [mt][lo/hi row]
    rs[0][0] = rs[0][1] = rs[1][0] = rs[1][1] = 0.f;

    #pragma unroll
    for (int mt = 0; mt < 2; mt++) {
        #pragma unroll
        for (int nt = 0; nt < 8; nt++) {
            int row = wm + mt * 16 + lr;
            int col = wn + nt * 8 + lc;
            float* cc = F.c[mt][nt];
            float e0 = ex2f(cc[0]), e1 = ex2f(cc[1]);
            float e2 = ex2f(cc[2]), e3 = ex2f(cc[3]);
            rs[mt][0] += e0 + e1;
            rs[mt][1] += e2 + e3;
            stage_sts(As, row,     col, pack_bf16x2(e0, e1));
            stage_sts(As, row + 8, col, pack_bf16x2(e2, e3));
        }
    }

    // reduce row sums across the 4 lanes sharing a row (lane&3)
    #pragma unroll
    for (int mt = 0; mt < 2; mt++)
        #pragma unroll
        for (int h = 0; h < 2; h++) {
            float v = rs[mt][h];
            v += __shfl_xor_sync(0xffffffffu, v, 1);
            v += __shfl_xor_sync(0xffffffffu, v, 2);
            if ((lane & 3) == 0) {
                int gr = b * SS + i0 + wm + mt * 16 + lr + h * 8;
                atomicAdd(&g_l[gr], v);
            }
        }
    __syncthreads();

    // coalesced store of the 128x128 bf16 tile into g_E
    uint4* Eg = reinterpret_cast<uint4*>(g_E);
    #pragma unroll
    for (int it = 0; it < 8; it++) {
        int idx = tid + 256 * it;
        int row = idx >> 4, chunk = idx & 15;
        Eg[((size_t)(b * SS + i0 + row)) * 256 + (j0 >> 3) + chunk] =
            reinterpret_cast<uint4*>(As)[tidx(row, chunk)];
    }
}

// ---------------------------------------------------------------------------
// uw: u = sigmoid(theta - mu*t)/l ; zero g_w and d_out
// ---------------------------------------------------------------------------
__global__ void uw_kernel(const float* __restrict__ t,
                          const float* __restrict__ theta,
                          const float* __restrict__ mu,
                          float* __restrict__ out) {
    int idx = blockIdx.x * 256 + threadIdx.x;
    if (idx < BB * SS) {
        int s = idx & (SS - 1);
        float z = theta[s] - mu[s] * t[idx];
        float tf = 1.f / (1.f + __expf(-z));
        g_u[idx] = tf / g_l[idx];
        g_w[idx] = 0.f;
    }
    if (idx < BB * DD) out[idx] = 0.f;
}

// ---------------------------------------------------------------------------
// wsum: w[b][j] = sum_i E[b][i][j] * u[b][i].  grid (32, 16), block 256.
// ---------------------------------------------------------------------------
__global__ void __launch_bounds__(256) wsum_kernel() {
    const int b = blockIdx.y, is = blockIdx.x, g = threadIdx.x;
    const uint4* Eb = reinterpret_cast<const uint4*>(g_E) + (size_t)b * SS * 256 + g;
    const float* ub = g_u + b * SS;

    float acc[8];
    #pragma unroll
    for (int p = 0; p < 8; p++) acc[p] = 0.f;

    int ib = is * 64;
    #pragma unroll 4
    for (int i = ib; i < ib + 64; i++) {
        uint4 ev = Eb[(size_t)i * 256];
        float uu = ub[i];
        const __nv_bfloat162* h = reinterpret_cast<const __nv_bfloat162*>(&ev);
        #pragma unroll
        for (int p = 0; p < 4; p++) {
            float2 f = __bfloat1622float2(h[p]);
            acc[2 * p]     += f.x * uu;
            acc[2 * p + 1] += f.y * uu;
        }
    }
    int j0 = b * SS + g * 8;
    #pragma unroll
    for (int p = 0; p < 8; p++) atomicAdd(&g_w[j0 + p], acc[p]);
}

// ---------------------------------------------------------------------------
// v: v[b][d] = sum_j w[b][j] * x[b][j][d].  grid (16, 16), block 128.
// ---------------------------------------------------------------------------
__global__ void v_kernel(const float* __restrict__ x, float* __restrict__ out) {
    const int b = blockIdx.y, js = blockIdx.x, d = threadIdx.x;
    const float* wb = g_w + b * SS;
    float acc = 0.f;
    int j0 = js * 128;
    #pragma unroll 4
    for (int j = j0; j < j0 + 128; j++)
        acc += wb[j] * x[((size_t)b * SS + j) * DD + d];
    atomicAdd(&out[b * DD + d], acc);
}

// ---------------------------------------------------------------------------
extern "C" void kernel_launch(void* const* d_in, const int* in_sizes, int n_in,
                              void* d_out, int out_size) {
    const float* x     = (const float*)d_in[0];
    const float* t     = (const float*)d_in[1];
    const float* Wq    = (const float*)d_in[2];
    const float* Wk    = (const float*)d_in[3];
    const float* theta = (const float*)d_in[4];
    const float* mu    = (const float*)d_in[5];
    float* out = (float*)d_out;

    static bool attr_done = false;
    if (!attr_done) {
        cudaFuncSetAttribute(proj_kernel,   cudaFuncAttributeMaxDynamicSharedMemorySize, 65536);
        cudaFuncSetAttribute(scores_kernel, cudaFuncAttributeMaxDynamicSharedMemorySize, 65536);
        attr_done = true;
    }

    prep_kernel<<<128, 256>>>(Wq, Wk);
    proj_kernel<<<dim3((BB * SS) / 128, 2), 256, 65536>>>(x);
    scores_kernel<<<dim3(SS / 128, SS / 128, BB), 256, 65536>>>();
    uw_kernel<<<(BB * SS + 255) / 256, 256>>>(t, theta, mu, out);
    wsum_kernel<<<dim3(32, BB), 256>>>();
    v_kernel<<<dim3(16, BB), 128>>>(x, out);
}

// round 6
// speedup vs baseline: 3.8891x; 1.0301x over previous
#include <cuda_runtime.h>
#include <cuda_fp16.h>
#include <cstdint>

#define BB 16
#define SS 2048
#define DD 128
#define UU 128

// ---------------------------------------------------------------------------
// Scratch (static __device__ — allocation-guard safe)
// ---------------------------------------------------------------------------
__device__ __half g_qh[(size_t)BB * SS * UU];   // q' = (x Wq)*log2e/sqrt(U), fp16 [row][u]
__device__ __half g_kh[(size_t)BB * SS * UU];   // k  =  x Wk, fp16 [row][u]
__device__ __half g_WT[256 * DD];               // [Wq*c | Wk] transposed: [n][d]
__device__ float g_l[BB * SS];
__device__ float g_w[BB * SS];

// ---------------------------------------------------------------------------
// helpers
// ---------------------------------------------------------------------------
__device__ __forceinline__ uint32_t smem_u32(const void* p) {
    uint32_t a;
    asm("{ .reg .u64 t; cvta.to.shared.u64 t, %1; cvt.u32.u64 %0, t; }" : "=r"(a) : "l"(p));
    return a;
}
__device__ __forceinline__ float ex2f(float x) {
    float r; asm("ex2.approx.f32 %0, %1;" : "=f"(r) : "f"(x)); return r;
}
__device__ __forceinline__ void ldmx4(uint32_t* r, uint32_t addr) {
    asm volatile("ldmatrix.sync.aligned.m8n8.x4.shared.b16 {%0,%1,%2,%3}, [%4];"
                 : "=r"(r[0]), "=r"(r[1]), "=r"(r[2]), "=r"(r[3]) : "r"(addr));
}
__device__ __forceinline__ void mma16816(float* c, const uint32_t* a, uint32_t b0, uint32_t b1) {
    asm volatile(
        "mma.sync.aligned.m16n8k16.row.col.f32.f16.f16.f32 "
        "{%0,%1,%2,%3}, {%4,%5,%6,%7}, {%8,%9}, {%0,%1,%2,%3};"
        : "+f"(c[0]), "+f"(c[1]), "+f"(c[2]), "+f"(c[3])
        : "r"(a[0]), "r"(a[1]), "r"(a[2]), "r"(a[3]), "r"(b0), "r"(b1));
}
__device__ __forceinline__ uint32_t pack_f16x2(float lo, float hi) {
    uint32_t r;
    asm("cvt.rn.f16x2.f32 %0, %1, %2;" : "=r"(r) : "f"(hi), "f"(lo));
    return r;
}

// Swizzled smem tile: rows x 16 uint4 chunks (256B/row), chunk ^= (row&7).
__device__ __forceinline__ int tidx(int row, int chunk) {
    return row * 16 + (chunk ^ (row & 7));
}
__device__ __forceinline__ uint32_t taddr(uint32_t base, int row, int chunk) {
    return base + (uint32_t)tidx(row, chunk) * 16u;
}

// ---------------------------------------------------------------------------
// prep: zero g_l/g_w/out; g_WT[n][d] = (n<128 ? Wq[d][n]*C : Wk[d][n-128]) fp16
// grid 128, block 256
// ---------------------------------------------------------------------------
__global__ void prep_kernel(const float* __restrict__ Wq, const float* __restrict__ Wk,
                            float* __restrict__ out) {
    const float C_FOLD = 0.12751744695704165f;  // log2(e)/sqrt(128)
    int idx = blockIdx.x * 256 + threadIdx.x;   // 0..32767
    g_l[idx] = 0.f;
    g_w[idx] = 0.f;
    if (idx < BB * DD) out[idx] = 0.f;
    int n = idx >> 7, d = idx & 127;
    float v = (n < 128) ? Wq[d * 128 + n] * C_FOLD : Wk[d * 128 + (n - 128)];
    g_WT[idx] = __float2half(v);
}

// ---------------------------------------------------------------------------
// GEMM core: per CTA 128x128 fp16 mma.sync, K=128 resident.
// 8 warps: wm=(wid&3)*32, wn=(wid>>2)*64; accumulators c[2][8][4].
// ---------------------------------------------------------------------------
struct Frag { float c[2][8][4]; };

__device__ __forceinline__ void gemm_128x128(uint32_t aBase, uint32_t bBase, Frag& F) {
    const int lane = threadIdx.x & 31, wid = threadIdx.x >> 5;
    const int wm = (wid & 3) * 32, wn = (wid >> 2) * 64;

    #pragma unroll
    for (int mt = 0; mt < 2; mt++)
        #pragma unroll
        for (int nt = 0; nt < 8; nt++)
            #pragma unroll
            for (int e = 0; e < 4; e++) F.c[mt][nt][e] = 0.f;

    const int l7 = lane & 7, lhi = lane >> 3;

    #pragma unroll
    for (int ks = 0; ks < 8; ks++) {
        uint32_t a[2][4];
        #pragma unroll
        for (int mt = 0; mt < 2; mt++) {
            int row = wm + mt * 16 + l7 + (lhi & 1) * 8;
            int chunk = 2 * ks + (lhi >> 1);
            ldmx4(a[mt], taddr(aBase, row, chunk));
        }
        uint32_t bfr[4][4];
        #pragma unroll
        for (int np = 0; np < 4; np++) {
            int row = wn + np * 16 + l7 + (lhi >> 1) * 8;
            int chunk = 2 * ks + (lhi & 1);
            ldmx4(bfr[np], taddr(bBase, row, chunk));
        }
        #pragma unroll
        for (int mt = 0; mt < 2; mt++)
            #pragma unroll
            for (int np = 0; np < 4; np++) {
                mma16816(F.c[mt][2 * np + 0], a[mt], bfr[np][0], bfr[np][1]);
                mma16816(F.c[mt][2 * np + 1], a[mt], bfr[np][2], bfr[np][3]);
            }
    }
}

__device__ __forceinline__ void stage_sts(char* sm, int row, int col, uint32_t v) {
    uint32_t byte = (uint32_t)tidx(row, col >> 3) * 16u + (uint32_t)(col & 7) * 2u;
    *reinterpret_cast<uint32_t*>(sm + byte) = v;
}

// ---------------------------------------------------------------------------
// proj: rows r0..r0+127 of x (fp32->fp16) @ g_WT half -> q' or k (fp16)
// grid (256, 2), block 256, smem 64KB
// ---------------------------------------------------------------------------
__global__ void __launch_bounds__(256) proj_kernel(const float* __restrict__ x) {
    extern __shared__ char sm[];
    char* As = sm;
    char* Bs = sm + 32768;
    uint32_t aBase = smem_u32(As), bBase = smem_u32(Bs);

    const int tid = threadIdx.x;
    const int r0 = blockIdx.x * 128;
    const int nsel = blockIdx.y;

    {
        const float4* xs = reinterpret_cast<const float4*>(x + (size_t)r0 * DD);
        #pragma unroll
        for (int it = 0; it < 8; it++) {
            int idx = tid + 256 * it;
            int row = idx >> 4, chunk = idx & 15;
            float4 f0 = xs[row * 32 + chunk * 2];
            float4 f1 = xs[row * 32 + chunk * 2 + 1];
            uint4 o;
            o.x = pack_f16x2(f0.x, f0.y);
            o.y = pack_f16x2(f0.z, f0.w);
            o.z = pack_f16x2(f1.x, f1.y);
            o.w = pack_f16x2(f1.z, f1.w);
            reinterpret_cast<uint4*>(As)[tidx(row, chunk)] = o;
        }
        const uint4* ws = reinterpret_cast<const uint4*>(g_WT) + nsel * 128 * 16;
        #pragma unroll
        for (int it = 0; it < 8; it++) {
            int idx = tid + 256 * it;
            int row = idx >> 4, chunk = idx & 15;
            reinterpret_cast<uint4*>(Bs)[tidx(row, chunk)] = ws[idx];
        }
    }
    __syncthreads();

    Frag F;
    gemm_128x128(aBase, bBase, F);
    __syncthreads();

    const int lane = tid & 31, wid = tid >> 5;
    const int wm = (wid & 3) * 32, wn = (wid >> 2) * 64;
    const int lr = lane >> 2, lc = (lane & 3) * 2;
    #pragma unroll
    for (int mt = 0; mt < 2; mt++)
        #pragma unroll
        for (int nt = 0; nt < 8; nt++) {
            int row = wm + mt * 16 + lr;
            int col = wn + nt * 8 + lc;
            float* cc = F.c[mt][nt];
            stage_sts(As, row,     col, pack_f16x2(cc[0], cc[1]));
            stage_sts(As, row + 8, col, pack_f16x2(cc[2], cc[3]));
        }
    __syncthreads();

    uint4* dst = reinterpret_cast<uint4*>(nsel ? g_kh : g_qh) + (size_t)r0 * 16;
    #pragma unroll
    for (int it = 0; it < 8; it++) {
        int idx = tid + 256 * it;
        int row = idx >> 4, chunk = idx & 15;
        dst[idx] = reinterpret_cast<uint4*>(As)[tidx(row, chunk)];
    }
}

// ---------------------------------------------------------------------------
// common tile loader for S1/S2
// ---------------------------------------------------------------------------
__device__ __forceinline__ void load_qk_tiles(char* As, char* Bs, int b, int i0, int j0, int tid) {
    const uint4* qs = reinterpret_cast<const uint4*>(g_qh) + (size_t)(b * SS + i0) * 16;
    const uint4* ks = reinterpret_cast<const uint4*>(g_kh) + (size_t)(b * SS + j0) * 16;
    #pragma unroll
    for (int it = 0; it < 8; it++) {
        int idx = tid + 256 * it;
        int row = idx >> 4, chunk = idx & 15;
        reinterpret_cast<uint4*>(As)[tidx(row, chunk)] = qs[idx];
        reinterpret_cast<uint4*>(Bs)[tidx(row, chunk)] = ks[idx];
    }
}

// ---------------------------------------------------------------------------
// S1: l_i += sum_j exp2(q'_i . k_j)    grid (16,16,16), block 256
// ---------------------------------------------------------------------------
__global__ void __launch_bounds__(256) s1_kernel() {
    extern __shared__ char sm[];
    char* As = sm;
    char* Bs = sm + 32768;
    uint32_t aBase = smem_u32(As), bBase = smem_u32(Bs);

    const int tid = threadIdx.x;
    const int b = blockIdx.z, i0 = blockIdx.y * 128, j0 = blockIdx.x * 128;

    load_qk_tiles(As, Bs, b, i0, j0, tid);
    __syncthreads();

    Frag F;
    gemm_128x128(aBase, bBase, F);

    const int lane = tid & 31, wid = tid >> 5;
    const int wm = (wid & 3) * 32;
    const int lr = lane >> 2;

    #pragma unroll
    for (int mt = 0; mt < 2; mt++) {
        float rlo = 0.f, rhi = 0.f;
        #pragma unroll
        for (int nt = 0; nt < 8; nt++) {
            float* cc = F.c[mt][nt];
            rlo += ex2f(cc[0]) + ex2f(cc[1]);
            rhi += ex2f(cc[2]) + ex2f(cc[3]);
        }
        // reduce over the 4 lanes sharing a row (lane&3)
        rlo += __shfl_xor_sync(0xffffffffu, rlo, 1);
        rlo += __shfl_xor_sync(0xffffffffu, rlo, 2);
        rhi += __shfl_xor_sync(0xffffffffu, rhi, 1);
        rhi += __shfl_xor_sync(0xffffffffu, rhi, 2);
        if ((lane & 3) == 0) {
            int gr = b * SS + i0 + wm + mt * 16 + lr;
            atomicAdd(&g_l[gr], rlo);
            atomicAdd(&g_l[gr + 8], rhi);
        }
    }
}

// ---------------------------------------------------------------------------
// S2: w_j += sum_i u_i * exp2(q'_i . k_j),  u_i = sigmoid(theta-mu*t)/l_i
// grid (16,16,16), block 256, smem 64KB + 512B for u
// ---------------------------------------------------------------------------
__global__ void __launch_bounds__(256) s2_kernel(const float* __restrict__ t,
                                                 const float* __restrict__ theta,
                                                 const float* __restrict__ mu) {
    extern __shared__ char sm[];
    char* As = sm;
    char* Bs = sm + 32768;
    float* us = reinterpret_cast<float*>(sm + 65536);
    uint32_t aBase = smem_u32(As), bBase = smem_u32(Bs);

    const int tid = threadIdx.x;
    const int b = blockIdx.z, i0 = blockIdx.y * 128, j0 = blockIdx.x * 128;

    load_qk_tiles(As, Bs, b, i0, j0, tid);
    if (tid < 128) {
        int i = i0 + tid;
        float z = theta[i] - mu[i] * t[b * SS + i];
        float tf = 1.f / (1.f + __expf(-z));
        us[tid] = tf / g_l[b * SS + i];
    }
    __syncthreads();

    Frag F;
    gemm_128x128(aBase, bBase, F);

    const int lane = tid & 31, wid = tid >> 5;
    const int wm = (wid & 3) * 32, wn = (wid >> 2) * 64;
    const int lr = lane >> 2;

    float s[8][2];
    #pragma unroll
    for (int nt = 0; nt < 8; nt++) { s[nt][0] = 0.f; s[nt][1] = 0.f; }

    #pragma unroll
    for (int mt = 0; mt < 2; mt++) {
        float ulo = us[wm + mt * 16 + lr];
        float uhi = us[wm + mt * 16 + lr + 8];
        #pragma unroll
        for (int nt = 0; nt < 8; nt++) {
            float* cc = F.c[mt][nt];
            s[nt][0] += ulo * ex2f(cc[0]) + uhi * ex2f(cc[2]);
            s[nt][1] += ulo * ex2f(cc[1]) + uhi * ex2f(cc[3]);
        }
    }

    // reduce over rows: lanes with equal (lane&3) — xor masks 4, 8, 16
    #pragma unroll
    for (int nt = 0; nt < 8; nt++)
        #pragma unroll
        for (int p = 0; p < 2; p++) {
            float v = s[nt][p];
            v += __shfl_xor_sync(0xffffffffu, v, 4);
            v += __shfl_xor_sync(0xffffffffu, v, 8);
            v += __shfl_xor_sync(0xffffffffu, v, 16);
            s[nt][p] = v;
        }
    if (lane < 4) {
        #pragma unroll
        for (int nt = 0; nt < 8; nt++) {
            int col = j0 + wn + nt * 8 + lane * 2;
            atomicAdd(&g_w[b * SS + col],     s[nt][0]);
            atomicAdd(&g_w[b * SS + col + 1], s[nt][1]);
        }
    }
}

// ---------------------------------------------------------------------------
// v: v[b][d] = sum_j w[b][j] * x[b][j][d].  grid (16, 16), block 128.
// ---------------------------------------------------------------------------
__global__ void v_kernel(const float* __restrict__ x, float* __restrict__ out) {
    const int b = blockIdx.y, js = blockIdx.x, d = threadIdx.x;
    const float* wb = g_w + b * SS;
    float acc = 0.f;
    int j0 = js * 128;
    #pragma unroll 4
    for (int j = j0; j < j0 + 128; j++)
        acc += wb[j] * x[((size_t)b * SS + j) * DD + d];
    atomicAdd(&out[b * DD + d], acc);
}

// ---------------------------------------------------------------------------
extern "C" void kernel_launch(void* const* d_in, const int* in_sizes, int n_in,
                              void* d_out, int out_size) {
    const float* x     = (const float*)d_in[0];
    const float* t     = (const float*)d_in[1];
    const float* Wq    = (const float*)d_in[2];
    const float* Wk    = (const float*)d_in[3];
    const float* theta = (const float*)d_in[4];
    const float* mu    = (const float*)d_in[5];
    float* out = (float*)d_out;

    static bool attr_done = false;
    if (!attr_done) {
        cudaFuncSetAttribute(proj_kernel, cudaFuncAttributeMaxDynamicSharedMemorySize, 65536);
        cudaFuncSetAttribute(s1_kernel,   cudaFuncAttributeMaxDynamicSharedMemorySize, 65536);
        cudaFuncSetAttribute(s2_kernel,   cudaFuncAttributeMaxDynamicSharedMemorySize, 66560);
        attr_done = true;
    }

    prep_kernel<<<128, 256>>>(Wq, Wk, out);
    proj_kernel<<<dim3((BB * SS) / 128, 2), 256, 65536>>>(x);
    s1_kernel<<<dim3(SS / 128, SS / 128, BB), 256, 65536>>>();
    s2_kernel<<<dim3(SS / 128, SS / 128, BB), 256, 66560>>>(t, theta, mu);
    v_kernel<<<dim3(16, BB), 128>>>(x, out);
}

// round 8
// speedup vs baseline: 4.5195x; 1.1621x over previous
#include <cuda_runtime.h>
#include <cuda_fp16.h>
#include <cstdint>

#define BB 16
#define SS 2048
#define DD 128
#define UU 128

// ---------------------------------------------------------------------------
// Scratch (static __device__ — allocation-guard safe)
// ---------------------------------------------------------------------------
__device__ __half g_qh[(size_t)BB * SS * UU];   // q' = (x Wq)*log2e/sqrt(U), fp16 [row][u]
__device__ __half g_kh[(size_t)BB * SS * UU];   // k  =  x Wk, fp16 [row][u]
__device__ __half g_WT[256 * DD];               // [Wq*c | Wk] transposed: [n][d]
__device__ float g_l[BB * SS];
__device__ float g_w[BB * SS];

// ---------------------------------------------------------------------------
// helpers
// ---------------------------------------------------------------------------
__device__ __forceinline__ uint32_t smem_u32(const void* p) {
    uint32_t a;
    asm("{ .reg .u64 t; cvta.to.shared.u64 t, %1; cvt.u32.u64 %0, t; }" : "=r"(a) : "l"(p));
    return a;
}
__device__ __forceinline__ float ex2f(float x) {
    float r; asm("ex2.approx.f32 %0, %1;" : "=f"(r) : "f"(x)); return r;
}
__device__ __forceinline__ void ldmx4(uint32_t* r, uint32_t addr) {
    asm volatile("ldmatrix.sync.aligned.m8n8.x4.shared.b16 {%0,%1,%2,%3}, [%4];"
                 : "=r"(r[0]), "=r"(r[1]), "=r"(r[2]), "=r"(r[3]) : "r"(addr));
}
__device__ __forceinline__ void mma16816(float* c, const uint32_t* a, uint32_t b0, uint32_t b1) {
    asm volatile(
        "mma.sync.aligned.m16n8k16.row.col.f32.f16.f16.f32 "
        "{%0,%1,%2,%3}, {%4,%5,%6,%7}, {%8,%9}, {%0,%1,%2,%3};"
        : "+f"(c[0]), "+f"(c[1]), "+f"(c[2]), "+f"(c[3])
        : "r"(a[0]), "r"(a[1]), "r"(a[2]), "r"(a[3]), "r"(b0), "r"(b1));
}
__device__ __forceinline__ uint32_t pack_f16x2(float lo, float hi) {
    uint32_t r;
    asm("cvt.rn.f16x2.f32 %0, %1, %2;" : "=r"(r) : "f"(hi), "f"(lo));
    return r;
}

// Swizzled smem tile: rows x 16 uint4 chunks (256B/row), chunk ^= (row&7).
__device__ __forceinline__ int tidx(int row, int chunk) {
    return row * 16 + (chunk ^ (row & 7));
}
__device__ __forceinline__ uint32_t taddr(uint32_t base, int row, int chunk) {
    return base + (uint32_t)tidx(row, chunk) * 16u;
}

// ---------------------------------------------------------------------------
// prep: zero g_l/g_w/out; g_WT[n][d] = (n<128 ? Wq[d][n]*C : Wk[d][n-128]) fp16
// ---------------------------------------------------------------------------
__global__ void prep_kernel(const float* __restrict__ Wq, const float* __restrict__ Wk,
                            float* __restrict__ out) {
    const float C_FOLD = 0.12751744695704165f;  // log2(e)/sqrt(128)
    int idx = blockIdx.x * 256 + threadIdx.x;   // 0..32767
    g_l[idx] = 0.f;
    g_w[idx] = 0.f;
    if (idx < BB * DD) out[idx] = 0.f;
    int n = idx >> 7, d = idx & 127;
    float v = (n < 128) ? Wq[d * 128 + n] * C_FOLD : Wk[d * 128 + (n - 128)];
    g_WT[idx] = __float2half(v);
}

// ---------------------------------------------------------------------------
// GEMM core: 128x128 fp16 mma.sync, K=128 resident, 4 warps, 64x64 warp tile.
// warp grid: wm=(wid&1)*64, wn=(wid>>1)*64. Acc c[4][8][4] (128 fp32/thread).
// Per K-step per warp: 8 ldmatrix.x4 feed 32 MMAs (mma:ldsm = 4.0).
// ---------------------------------------------------------------------------
struct Frag { float c[4][8][4]; };

__device__ __forceinline__ void gemm_core(uint32_t aBase, uint32_t bBase, Frag& F) {
    const int lane = threadIdx.x & 31, wid = threadIdx.x >> 5;
    const int wm = (wid & 1) * 64, wn = (wid >> 1) * 64;

    #pragma unroll
    for (int mt = 0; mt < 4; mt++)
        #pragma unroll
        for (int nt = 0; nt < 8; nt++)
            #pragma unroll
            for (int e = 0; e < 4; e++) F.c[mt][nt][e] = 0.f;

    const int l7 = lane & 7, lhi = lane >> 3;

    #pragma unroll
    for (int ks = 0; ks < 8; ks++) {
        uint32_t a[4][4];
        #pragma unroll
        for (int mt = 0; mt < 4; mt++) {
            int row = wm + mt * 16 + l7 + (lhi & 1) * 8;
            int chunk = 2 * ks + (lhi >> 1);
            ldmx4(a[mt], taddr(aBase, row, chunk));
        }
        uint32_t bfr[4][4];
        #pragma unroll
        for (int np = 0; np < 4; np++) {
            int row = wn + np * 16 + l7 + (lhi >> 1) * 8;
            int chunk = 2 * ks + (lhi & 1);
            ldmx4(bfr[np], taddr(bBase, row, chunk));
        }
        #pragma unroll
        for (int mt = 0; mt < 4; mt++)
            #pragma unroll
            for (int np = 0; np < 4; np++) {
                mma16816(F.c[mt][2 * np + 0], a[mt], bfr[np][0], bfr[np][1]);
                mma16816(F.c[mt][2 * np + 1], a[mt], bfr[np][2], bfr[np][3]);
            }
    }
}

__device__ __forceinline__ void stage_sts(char* sm, int row, int col, uint32_t v) {
    uint32_t byte = (uint32_t)tidx(row, col >> 3) * 16u + (uint32_t)(col & 7) * 2u;
    *reinterpret_cast<uint32_t*>(sm + byte) = v;
}

// ---------------------------------------------------------------------------
// proj: rows r0..r0+127 of x (fp32->fp16) @ g_WT half -> q' or k (fp16)
// grid (256, 2), block 128, smem 64KB
// ---------------------------------------------------------------------------
__global__ void __launch_bounds__(128) proj_kernel(const float* __restrict__ x) {
    extern __shared__ char sm[];
    char* As = sm;
    char* Bs = sm + 32768;
    uint32_t aBase = smem_u32(As), bBase = smem_u32(Bs);

    const int tid = threadIdx.x;
    const int r0 = blockIdx.x * 128;
    const int nsel = blockIdx.y;

    {
        const float4* xs = reinterpret_cast<const float4*>(x + (size_t)r0 * DD);
        #pragma unroll
        for (int it = 0; it < 16; it++) {
            int idx = tid + 128 * it;             // 0..2047
            int row = idx >> 4, chunk = idx & 15;
            float4 f0 = xs[row * 32 + chunk * 2];
            float4 f1 = xs[row * 32 + chunk * 2 + 1];
            uint4 o;
            o.x = pack_f16x2(f0.x, f0.y);
            o.y = pack_f16x2(f0.z, f0.w);
            o.z = pack_f16x2(f1.x, f1.y);
            o.w = pack_f16x2(f1.z, f1.w);
            reinterpret_cast<uint4*>(As)[tidx(row, chunk)] = o;
        }
        const uint4* ws = reinterpret_cast<const uint4*>(g_WT) + nsel * 128 * 16;
        #pragma unroll
        for (int it = 0; it < 16; it++) {
            int idx = tid + 128 * it;
            int row = idx >> 4, chunk = idx & 15;
            reinterpret_cast<uint4*>(Bs)[tidx(row, chunk)] = ws[idx];
        }
    }
    __syncthreads();

    Frag F;
    gemm_core(aBase, bBase, F);
    __syncthreads();

    const int lane = tid & 31, wid = tid >> 5;
    const int wm = (wid & 1) * 64, wn = (wid >> 1) * 64;
    const int lr = lane >> 2, lc = (lane & 3) * 2;
    #pragma unroll
    for (int mt = 0; mt < 4; mt++)
        #pragma unroll
        for (int nt = 0; nt < 8; nt++) {
            int row = wm + mt * 16 + lr;
            int col = wn + nt * 8 + lc;
            float* cc = F.c[mt][nt];
            stage_sts(As, row,     col, pack_f16x2(cc[0], cc[1]));
            stage_sts(As, row + 8, col, pack_f16x2(cc[2], cc[3]));
        }
    __syncthreads();

    uint4* dst = reinterpret_cast<uint4*>(nsel ? g_kh : g_qh) + (size_t)r0 * 16;
    #pragma unroll
    for (int it = 0; it < 16; it++) {
        int idx = tid + 128 * it;
        int row = idx >> 4, chunk = idx & 15;
        dst[idx] = reinterpret_cast<uint4*>(As)[tidx(row, chunk)];
    }
}

// ---------------------------------------------------------------------------
// tile loader for S1/S2 (block = 128 threads)
// ---------------------------------------------------------------------------
__device__ __forceinline__ void load_qk_tiles(char* As, char* Bs, int b, int i0, int j0, int tid) {
    const uint4* qs = reinterpret_cast<const uint4*>(g_qh) + (size_t)(b * SS + i0) * 16;
    const uint4* ks = reinterpret_cast<const uint4*>(g_kh) + (size_t)(b * SS + j0) * 16;
    #pragma unroll
    for (int it = 0; it < 16; it++) {
        int idx = tid + 128 * it;
        int row = idx >> 4, chunk = idx & 15;
        reinterpret_cast<uint4*>(As)[tidx(row, chunk)] = qs[idx];
        reinterpret_cast<uint4*>(Bs)[tidx(row, chunk)] = ks[idx];
    }
}

// ---------------------------------------------------------------------------
// S1: l_i += sum_j exp2(q'_i . k_j)    grid (16,16,16), block 128
// ---------------------------------------------------------------------------
__global__ void __launch_bounds__(128) s1_kernel() {
    extern __shared__ char sm[];
    char* As = sm;
    char* Bs = sm + 32768;
    uint32_t aBase = smem_u32(As), bBase = smem_u32(Bs);

    const int tid = threadIdx.x;
    const int b = blockIdx.z, i0 = blockIdx.y * 128, j0 = blockIdx.x * 128;

    load_qk_tiles(As, Bs, b, i0, j0, tid);
    __syncthreads();

    Frag F;
    gemm_core(aBase, bBase, F);

    const int lane = tid & 31, wid = tid >> 5;
    const int wm = (wid & 1) * 64;
    const int lr = lane >> 2;

    #pragma unroll
    for (int mt = 0; mt < 4; mt++) {
        float rlo = 0.f, rhi = 0.f;
        #pragma unroll
        for (int nt = 0; nt < 8; nt++) {
            float* cc = F.c[mt][nt];
            rlo += ex2f(cc[0]) + ex2f(cc[1]);
            rhi += ex2f(cc[2]) + ex2f(cc[3]);
        }
        rlo += __shfl_xor_sync(0xffffffffu, rlo, 1);
        rlo += __shfl_xor_sync(0xffffffffu, rlo, 2);
        rhi += __shfl_xor_sync(0xffffffffu, rhi, 1);
        rhi += __shfl_xor_sync(0xffffffffu, rhi, 2);
        if ((lane & 3) == 0) {
            int gr = b * SS + i0 + wm + mt * 16 + lr;
            atomicAdd(&g_l[gr], rlo);
            atomicAdd(&g_l[gr + 8], rhi);
        }
    }
}

// ---------------------------------------------------------------------------
// S2: w_j += sum_i u_i * exp2(q'_i . k_j),  u_i = sigmoid(theta-mu*t)/l_i
// grid (16,16,16), block 128, smem 64KB + 512B
// ---------------------------------------------------------------------------
__global__ void __launch_bounds__(128) s2_kernel(const float* __restrict__ t,
                                                 const float* __restrict__ theta,
                                                 const float* __restrict__ mu) {
    extern __shared__ char sm[];
    char* As = sm;
    char* Bs = sm + 32768;
    float* us = reinterpret_cast<float*>(sm + 65536);
    uint32_t aBase = smem_u32(As), bBase = smem_u32(Bs);

    const int tid = threadIdx.x;
    const int b = blockIdx.z, i0 = blockIdx.y * 128, j0 = blockIdx.x * 128;

    load_qk_tiles(As, Bs, b, i0, j0, tid);
    {
        int i = i0 + tid;
        float z = theta[i] - mu[i] * t[b * SS + i];
        float tf = 1.f / (1.f + __expf(-z));
        us[tid] = tf / g_l[b * SS + i];
    }
    __syncthreads();

    Frag F;
    gemm_core(aBase, bBase, F);

    const int lane = tid & 31, wid = tid >> 5;
    const int wm = (wid & 1) * 64, wn = (wid >> 1) * 64;
    const int lr = lane >> 2;

    float s[8][2];
    #pragma unroll
    for (int nt = 0; nt < 8; nt++) { s[nt][0] = 0.f; s[nt][1] = 0.f; }

    #pragma unroll
    for (int mt = 0; mt < 4; mt++) {
        float ulo = us[wm + mt * 16 + lr];
        float uhi = us[wm + mt * 16 + lr + 8];
        #pragma unroll
        for (int nt = 0; nt < 8; nt++) {
            float* cc = F.c[mt][nt];
            s[nt][0] += ulo * ex2f(cc[0]) + uhi * ex2f(cc[2]);
            s[nt][1] += ulo * ex2f(cc[1]) + uhi * ex2f(cc[3]);
        }
    }

    // reduce over rows: lanes with equal (lane&3) — xor masks 4, 8, 16
    #pragma unroll
    for (int nt = 0; nt < 8; nt++)
        #pragma unroll
        for (int p = 0; p < 2; p++) {
            float v = s[nt][p];
            v += __shfl_xor_sync(0xffffffffu, v, 4);
            v += __shfl_xor_sync(0xffffffffu, v, 8);
            v += __shfl_xor_sync(0xffffffffu, v, 16);
            s[nt][p] = v;
        }
    if (lane < 4) {
        #pragma unroll
        for (int nt = 0; nt < 8; nt++) {
            int col = j0 + wn + nt * 8 + lane * 2;
            atomicAdd(&g_w[b * SS + col],     s[nt][0]);
            atomicAdd(&g_w[b * SS + col + 1], s[nt][1]);
        }
    }
}

// ---------------------------------------------------------------------------
// v: v[b][d] = sum_j w[b][j] * x[b][j][d].  grid (16, 16), block 128.
// ---------------------------------------------------------------------------
__global__ void v_kernel(const float* __restrict__ x, float* __restrict__ out) {
    const int b = blockIdx.y, js = blockIdx.x, d = threadIdx.x;
    const float* wb = g_w + b * SS;
    float acc = 0.f;
    int j0 = js * 128;
    #pragma unroll 4
    for (int j = j0; j < j0 + 128; j++)
        acc += wb[j] * x[((size_t)b * SS + j) * DD + d];
    atomicAdd(&out[b * DD + d], acc);
}

// ---------------------------------------------------------------------------
extern "C" void kernel_launch(void* const* d_in, const int* in_sizes, int n_in,
                              void* d_out, int out_size) {
    const float* x     = (const float*)d_in[0];
    const float* t     = (const float*)d_in[1];
    const float* Wq    = (const float*)d_in[2];
    const float* Wk    = (const float*)d_in[3];
    const float* theta = (const float*)d_in[4];
    const float* mu    = (const float*)d_in[5];
    float* out = (float*)d_out;

    static bool attr_done = false;
    if (!attr_done) {
        cudaFuncSetAttribute(proj_kernel, cudaFuncAttributeMaxDynamicSharedMemorySize, 65536);
        cudaFuncSetAttribute(s1_kernel,   cudaFuncAttributeMaxDynamicSharedMemorySize, 65536);
        cudaFuncSetAttribute(s2_kernel,   cudaFuncAttributeMaxDynamicSharedMemorySize, 66560);
        attr_done = true;
    }

    prep_kernel<<<128, 256>>>(Wq, Wk, out);
    proj_kernel<<<dim3((BB * SS) / 128, 2), 128, 65536>>>(x);
    s1_kernel<<<dim3(SS / 128, SS / 128, BB), 128, 65536>>>();
    s2_kernel<<<dim3(SS / 128, SS / 128, BB), 128, 66560>>>(t, theta, mu);
    v_kernel<<<dim3(16, BB), 128>>>(x, out);
}